// round 14
// baseline (speedup 1.0000x reference)
#include <cuda_runtime.h>
#include <math.h>

// Problem constants (fixed shapes from setup_inputs)
#define BSZ   4
#define SEQ   8192
#define DIM   1024
#define DIN   2048
#define MTOK  (BSZ * SEQ)          // 32768 tokens

// ---------------------------------------------------------------------------
// Scratch (no cudaMalloc allowed): 134MB + 268MB + 268MB
// ---------------------------------------------------------------------------
__device__ float g_XN[(size_t)MTOK * DIM];   // rmsnorm(x)
__device__ float g_A [(size_t)MTOK * DIN];   // sigmoid gate a
__device__ float g_B [(size_t)MTOK * DIN];   // silu b, then h (in place)

// ---------------------------------------------------------------------------
// Packed f32x2 helpers (B300: FFMA2 doubles FP32 throughput vs scalar FFMA)
// ---------------------------------------------------------------------------
__device__ __forceinline__ unsigned long long pk2(float lo, float hi) {
    unsigned long long r;
    asm("mov.b64 %0, {%1, %2};" : "=l"(r) : "f"(lo), "f"(hi));
    return r;
}
__device__ __forceinline__ void fma2(unsigned long long& c,
                                     unsigned long long a,
                                     unsigned long long b) {
    asm("fma.rn.f32x2 %0, %1, %2, %3;" : "=l"(c) : "l"(a), "l"(b), "l"(c));
}
__device__ __forceinline__ void upk2(unsigned long long v, float& lo, float& hi) {
    asm("mov.b64 {%0, %1}, %2;" : "=f"(lo), "=f"(hi) : "l"(v));
}

// ---------------------------------------------------------------------------
// Kernel 1: RMSNorm. One warp per token row (D=1024 = 32 lanes x 8 float4).
// ---------------------------------------------------------------------------
__global__ void rmsnorm_kernel(const float* __restrict__ x,
                               const float* __restrict__ w,
                               float* __restrict__ xn) {
    int gwarp = (blockIdx.x * blockDim.x + threadIdx.x) >> 5;
    int lane  = threadIdx.x & 31;
    if (gwarp >= MTOK) return;

    const float4* xr = reinterpret_cast<const float4*>(x) + (size_t)gwarp * (DIM / 4);
    float4 v[8];
    float ss = 0.0f;
#pragma unroll
    for (int j = 0; j < 8; j++) {
        v[j] = xr[lane + j * 32];
        ss += v[j].x * v[j].x + v[j].y * v[j].y + v[j].z * v[j].z + v[j].w * v[j].w;
    }
#pragma unroll
    for (int o = 16; o > 0; o >>= 1) ss += __shfl_xor_sync(0xffffffffu, ss, o);

    float rstd = rsqrtf(ss * (1.0f / DIM) + 1e-6f);

    const float4* wr = reinterpret_cast<const float4*>(w);
    float4* xo = reinterpret_cast<float4*>(xn) + (size_t)gwarp * (DIM / 4);
#pragma unroll
    for (int j = 0; j < 8; j++) {
        float4 wv = wr[lane + j * 32];
        float4 o;
        o.x = v[j].x * rstd * wv.x;
        o.y = v[j].y * rstd * wv.y;
        o.z = v[j].z * rstd * wv.z;
        o.w = v[j].w * rstd * wv.w;
        xo[lane + j * 32] = o;
    }
}

// ---------------------------------------------------------------------------
// SGEMM: C[M,N] = A[M,K] (row-major) * Bw[N,K]^T (row-major, K contiguous).
// BM=BN=128, BK=16, thread tile 8x8, 256 threads, double-buffered smem,
// FFMA2 inner product.
// MODE 0: A = g_XN, epilogue = +bias, sigmoid -> g_A / silu -> g_B
// MODE 1: A = g_B (h), epilogue = +bias +x residual -> outC
// ---------------------------------------------------------------------------
template <int MODE, int Nv, int Kv>
__global__ __launch_bounds__(256, 2)
void sgemm_kernel(const float* __restrict__ Bw,
                  const float* __restrict__ bias,
                  const float* __restrict__ Xres,
                  float* __restrict__ outC) {
    __shared__ __align__(16) float As[2][16][132];
    __shared__ __align__(16) float Bs[2][16][132];

    const float* __restrict__ A = (MODE == 0) ? g_XN : g_B;

    const int tid  = threadIdx.x;
    const int tx   = tid & 15;
    const int ty   = tid >> 4;
    const int lrow = tid >> 2;          // 0..63
    const int lcol = (tid & 3) << 2;    // 0,4,8,12

    const size_t aBase = (size_t)(blockIdx.y * 128 + lrow) * Kv + lcol;
    const size_t bBase = (size_t)(blockIdx.x * 128 + lrow) * Kv + lcol;

    unsigned long long acc[8][4];
#pragma unroll
    for (int i = 0; i < 8; i++)
#pragma unroll
        for (int j = 0; j < 4; j++) acc[i][j] = 0ull;

    // ---- preload tile 0 ----
    float4 pa0 = *(const float4*)(A  + aBase);
    float4 pa1 = *(const float4*)(A  + aBase + (size_t)64 * Kv);
    float4 pb0 = *(const float4*)(Bw + bBase);
    float4 pb1 = *(const float4*)(Bw + bBase + (size_t)64 * Kv);

    As[0][lcol + 0][lrow]      = pa0.x; As[0][lcol + 1][lrow]      = pa0.y;
    As[0][lcol + 2][lrow]      = pa0.z; As[0][lcol + 3][lrow]      = pa0.w;
    As[0][lcol + 0][lrow + 64] = pa1.x; As[0][lcol + 1][lrow + 64] = pa1.y;
    As[0][lcol + 2][lrow + 64] = pa1.z; As[0][lcol + 3][lrow + 64] = pa1.w;
    Bs[0][lcol + 0][lrow]      = pb0.x; Bs[0][lcol + 1][lrow]      = pb0.y;
    Bs[0][lcol + 2][lrow]      = pb0.z; Bs[0][lcol + 3][lrow]      = pb0.w;
    Bs[0][lcol + 0][lrow + 64] = pb1.x; Bs[0][lcol + 1][lrow + 64] = pb1.y;
    Bs[0][lcol + 2][lrow + 64] = pb1.z; Bs[0][lcol + 3][lrow + 64] = pb1.w;
    __syncthreads();

    const int KT = Kv >> 4;
    int buf = 0;
    for (int kt = 0; kt < KT; kt++) {
        if (kt + 1 < KT) {
            size_t off = (size_t)(kt + 1) * 16;
            pa0 = *(const float4*)(A  + aBase + off);
            pa1 = *(const float4*)(A  + aBase + off + (size_t)64 * Kv);
            pb0 = *(const float4*)(Bw + bBase + off);
            pb1 = *(const float4*)(Bw + bBase + off + (size_t)64 * Kv);
        }
#pragma unroll
        for (int k = 0; k < 16; k++) {
            float4 a0 = *(const float4*)(&As[buf][k][ty * 8]);
            float4 a1 = *(const float4*)(&As[buf][k][ty * 8 + 4]);
            ulonglong2 b0 = *(const ulonglong2*)(&Bs[buf][k][tx * 8]);
            ulonglong2 b1 = *(const ulonglong2*)(&Bs[buf][k][tx * 8 + 4]);
            float av[8] = {a0.x, a0.y, a0.z, a0.w, a1.x, a1.y, a1.z, a1.w};
#pragma unroll
            for (int i = 0; i < 8; i++) {
                unsigned long long ad = pk2(av[i], av[i]);
                fma2(acc[i][0], ad, b0.x);
                fma2(acc[i][1], ad, b0.y);
                fma2(acc[i][2], ad, b1.x);
                fma2(acc[i][3], ad, b1.y);
            }
        }
        if (kt + 1 < KT) {
            int nb = buf ^ 1;
            As[nb][lcol + 0][lrow]      = pa0.x; As[nb][lcol + 1][lrow]      = pa0.y;
            As[nb][lcol + 2][lrow]      = pa0.z; As[nb][lcol + 3][lrow]      = pa0.w;
            As[nb][lcol + 0][lrow + 64] = pa1.x; As[nb][lcol + 1][lrow + 64] = pa1.y;
            As[nb][lcol + 2][lrow + 64] = pa1.z; As[nb][lcol + 3][lrow + 64] = pa1.w;
            Bs[nb][lcol + 0][lrow]      = pb0.x; Bs[nb][lcol + 1][lrow]      = pb0.y;
            Bs[nb][lcol + 2][lrow]      = pb0.z; Bs[nb][lcol + 3][lrow]      = pb0.w;
            Bs[nb][lcol + 0][lrow + 64] = pb1.x; Bs[nb][lcol + 1][lrow + 64] = pb1.y;
            Bs[nb][lcol + 2][lrow + 64] = pb1.z; Bs[nb][lcol + 3][lrow + 64] = pb1.w;
            __syncthreads();
            buf = nb;
        }
    }

    // ---- epilogue ----
    float c[8][8];
#pragma unroll
    for (int i = 0; i < 8; i++)
#pragma unroll
        for (int j = 0; j < 4; j++) upk2(acc[i][j], c[i][2 * j], c[i][2 * j + 1]);

    const int row0 = blockIdx.y * 128 + ty * 8;
    const int col0 = blockIdx.x * 128 + tx * 8;

    float4 bb0 = *(const float4*)(bias + col0);
    float4 bb1 = *(const float4*)(bias + col0 + 4);
    float bv[8] = {bb0.x, bb0.y, bb0.z, bb0.w, bb1.x, bb1.y, bb1.z, bb1.w};

    if (MODE == 0) {
        const bool isA = (col0 < DIN);
        float* base = isA ? g_A : g_B;
        const int cc = isA ? col0 : (col0 - DIN);
#pragma unroll
        for (int i = 0; i < 8; i++) {
            float o[8];
#pragma unroll
            for (int j = 0; j < 8; j++) {
                float v = c[i][j] + bv[j];
                float s = __fdividef(1.0f, 1.0f + __expf(-v));
                o[j] = isA ? s : v * s;   // sigmoid | silu
            }
            float* p = base + (size_t)(row0 + i) * DIN + cc;
            *(float4*)(p)     = make_float4(o[0], o[1], o[2], o[3]);
            *(float4*)(p + 4) = make_float4(o[4], o[5], o[6], o[7]);
        }
    } else {
#pragma unroll
        for (int i = 0; i < 8; i++) {
            size_t off = (size_t)(row0 + i) * Nv + col0;
            float4 x0 = *(const float4*)(Xres + off);
            float4 x1 = *(const float4*)(Xres + off + 4);
            float4 o0, o1;
            o0.x = c[i][0] + bv[0] + x0.x;
            o0.y = c[i][1] + bv[1] + x0.y;
            o0.z = c[i][2] + bv[2] + x0.z;
            o0.w = c[i][3] + bv[3] + x0.w;
            o1.x = c[i][4] + bv[4] + x1.x;
            o1.y = c[i][5] + bv[5] + x1.y;
            o1.z = c[i][6] + bv[6] + x1.z;
            o1.w = c[i][7] + bv[7] + x1.w;
            *(float4*)(outC + off)     = o0;
            *(float4*)(outC + off + 4) = o1;
        }
    }
}

// ---------------------------------------------------------------------------
// Kernel 3: recurrent scan. One thread per (batch, channel); h written into
// g_B in place. Coalesced: consecutive threads = consecutive channels.
// ---------------------------------------------------------------------------
__global__ void scan_kernel(const float* __restrict__ h_prev,
                            float* __restrict__ hlast_out) {
    int t = blockIdx.x * blockDim.x + threadIdx.x;
    if (t >= BSZ * DIN) return;
    int b = t / DIN;
    int e = t - b * DIN;

    float h = h_prev[t];
    size_t idx = (size_t)b * SEQ * DIN + e;
#pragma unroll 8
    for (int n = 0; n < SEQ; n++) {
        float a  = g_A[idx];
        float bb = g_B[idx];
        h = fmaf(a, h, bb);
        g_B[idx] = h;
        idx += DIN;
    }
    hlast_out[t] = h;
}

// ---------------------------------------------------------------------------
// Launch
// ---------------------------------------------------------------------------
extern "C" void kernel_launch(void* const* d_in, const int* in_sizes, int n_in,
                              void* d_out, int out_size) {
    const float* x      = (const float*)d_in[0];   // (4, 8192, 1024)
    const float* h_prev = (const float*)d_in[1];   // (4, 2048)
    const float* norm_w = (const float*)d_in[2];   // (1024,)
    const float* W_in   = (const float*)d_in[3];   // (4096, 1024)
    const float* b_in   = (const float*)d_in[4];   // (4096,)
    const float* W_out  = (const float*)d_in[5];   // (1024, 2048)
    const float* b_out  = (const float*)d_in[6];   // (1024,)
    float* out = (float*)d_out;                    // out (4,8192,1024) then h_last (4,2048)

    float* pXN;
    cudaGetSymbolAddress((void**)&pXN, g_XN);
    (void)pXN; (void)in_sizes; (void)n_in; (void)out_size;

    // 1. RMSNorm: 32768 rows, 1 warp each
    rmsnorm_kernel<<<MTOK / 8, 256>>>(x, norm_w, pXN);

    // 2. GEMM1 + gate activations: [32768 x 1024] * [4096 x 1024]^T
    dim3 g1((2 * DIN) / 128, MTOK / 128);
    sgemm_kernel<0, 2 * DIN, DIM><<<g1, 256>>>(W_in, b_in, nullptr, nullptr);

    // 3. Recurrent scan (h stored in g_B in place, h_last to tail of d_out)
    scan_kernel<<<(BSZ * DIN) / 128, 128>>>(h_prev, out + (size_t)MTOK * DIM);

    // 4. GEMM2 + bias + residual: [32768 x 2048] * [1024 x 2048]^T + x
    dim3 g2(DIM / 128, MTOK / 128);
    sgemm_kernel<1, DIM, DIN><<<g2, 256>>>(W_out, b_out, x, out);
}

// round 15
// speedup vs baseline: 1.0411x; 1.0411x over previous
#include <cuda_runtime.h>
#include <math.h>

// Problem constants (fixed shapes from setup_inputs)
#define BSZ   4
#define SEQ   8192
#define DIM   1024
#define DIN   2048
#define MTOK  (BSZ * SEQ)          // 32768 tokens

// ---------------------------------------------------------------------------
// Scratch (no cudaMalloc allowed): 134MB + 268MB + 268MB
// ---------------------------------------------------------------------------
__device__ float g_XN[(size_t)MTOK * DIM];   // rmsnorm(x)
__device__ float g_A [(size_t)MTOK * DIN];   // sigmoid gate a
__device__ float g_B [(size_t)MTOK * DIN];   // silu b, then h (in place)

// ---------------------------------------------------------------------------
// Packed f32x2 helpers (B300: FFMA2 doubles FP32 throughput vs scalar FFMA)
// ---------------------------------------------------------------------------
__device__ __forceinline__ unsigned long long pk2(float lo, float hi) {
    unsigned long long r;
    asm("mov.b64 %0, {%1, %2};" : "=l"(r) : "f"(lo), "f"(hi));
    return r;
}
__device__ __forceinline__ void fma2(unsigned long long& c,
                                     unsigned long long a,
                                     unsigned long long b) {
    asm("fma.rn.f32x2 %0, %1, %2, %3;" : "=l"(c) : "l"(a), "l"(b), "l"(c));
}
__device__ __forceinline__ void upk2(unsigned long long v, float& lo, float& hi) {
    asm("mov.b64 {%0, %1}, %2;" : "=f"(lo), "=f"(hi) : "l"(v));
}

// ---------------------------------------------------------------------------
// Kernel 1: RMSNorm. One warp per token row (D=1024 = 32 lanes x 8 float4).
// ---------------------------------------------------------------------------
__global__ void rmsnorm_kernel(const float* __restrict__ x,
                               const float* __restrict__ w,
                               float* __restrict__ xn) {
    int gwarp = (blockIdx.x * blockDim.x + threadIdx.x) >> 5;
    int lane  = threadIdx.x & 31;
    if (gwarp >= MTOK) return;

    const float4* xr = reinterpret_cast<const float4*>(x) + (size_t)gwarp * (DIM / 4);
    float4 v[8];
    float ss = 0.0f;
#pragma unroll
    for (int j = 0; j < 8; j++) {
        v[j] = xr[lane + j * 32];
        ss += v[j].x * v[j].x + v[j].y * v[j].y + v[j].z * v[j].z + v[j].w * v[j].w;
    }
#pragma unroll
    for (int o = 16; o > 0; o >>= 1) ss += __shfl_xor_sync(0xffffffffu, ss, o);

    float rstd = rsqrtf(ss * (1.0f / DIM) + 1e-6f);

    const float4* wr = reinterpret_cast<const float4*>(w);
    float4* xo = reinterpret_cast<float4*>(xn) + (size_t)gwarp * (DIM / 4);
#pragma unroll
    for (int j = 0; j < 8; j++) {
        float4 wv = wr[lane + j * 32];
        float4 o;
        o.x = v[j].x * rstd * wv.x;
        o.y = v[j].y * rstd * wv.y;
        o.z = v[j].z * rstd * wv.z;
        o.w = v[j].w * rstd * wv.w;
        xo[lane + j * 32] = o;
    }
}

// ---------------------------------------------------------------------------
// SGEMM: C[M,N] = A[M,K] (row-major) * Bw[N,K]^T (row-major, K contiguous).
// BM=BN=128, BK=16, thread tile 8x8, 256 threads, double-buffered smem,
// FFMA2 inner product.
// MODE 0: A = g_XN, epilogue = +bias, sigmoid -> g_A / silu -> g_B
// MODE 1: A = g_B (h), epilogue = +bias +x residual -> outC
// ---------------------------------------------------------------------------
template <int MODE, int Nv, int Kv>
__global__ __launch_bounds__(256, 2)
void sgemm_kernel(const float* __restrict__ Bw,
                  const float* __restrict__ bias,
                  const float* __restrict__ Xres,
                  float* __restrict__ outC) {
    __shared__ __align__(16) float As[2][16][132];
    __shared__ __align__(16) float Bs[2][16][132];

    const float* __restrict__ A = (MODE == 0) ? g_XN : g_B;

    const int tid  = threadIdx.x;
    const int tx   = tid & 15;
    const int ty   = tid >> 4;
    const int lrow = tid >> 2;          // 0..63
    const int lcol = (tid & 3) << 2;    // 0,4,8,12

    const size_t aBase = (size_t)(blockIdx.y * 128 + lrow) * Kv + lcol;
    const size_t bBase = (size_t)(blockIdx.x * 128 + lrow) * Kv + lcol;

    unsigned long long acc[8][4];
#pragma unroll
    for (int i = 0; i < 8; i++)
#pragma unroll
        for (int j = 0; j < 4; j++) acc[i][j] = 0ull;

    // ---- preload tile 0 ----
    float4 pa0 = *(const float4*)(A  + aBase);
    float4 pa1 = *(const float4*)(A  + aBase + (size_t)64 * Kv);
    float4 pb0 = *(const float4*)(Bw + bBase);
    float4 pb1 = *(const float4*)(Bw + bBase + (size_t)64 * Kv);

    As[0][lcol + 0][lrow]      = pa0.x; As[0][lcol + 1][lrow]      = pa0.y;
    As[0][lcol + 2][lrow]      = pa0.z; As[0][lcol + 3][lrow]      = pa0.w;
    As[0][lcol + 0][lrow + 64] = pa1.x; As[0][lcol + 1][lrow + 64] = pa1.y;
    As[0][lcol + 2][lrow + 64] = pa1.z; As[0][lcol + 3][lrow + 64] = pa1.w;
    Bs[0][lcol + 0][lrow]      = pb0.x; Bs[0][lcol + 1][lrow]      = pb0.y;
    Bs[0][lcol + 2][lrow]      = pb0.z; Bs[0][lcol + 3][lrow]      = pb0.w;
    Bs[0][lcol + 0][lrow + 64] = pb1.x; Bs[0][lcol + 1][lrow + 64] = pb1.y;
    Bs[0][lcol + 2][lrow + 64] = pb1.z; Bs[0][lcol + 3][lrow + 64] = pb1.w;
    __syncthreads();

    const int KT = Kv >> 4;
    int buf = 0;
    for (int kt = 0; kt < KT; kt++) {
        if (kt + 1 < KT) {
            size_t off = (size_t)(kt + 1) * 16;
            pa0 = *(const float4*)(A  + aBase + off);
            pa1 = *(const float4*)(A  + aBase + off + (size_t)64 * Kv);
            pb0 = *(const float4*)(Bw + bBase + off);
            pb1 = *(const float4*)(Bw + bBase + off + (size_t)64 * Kv);
        }
#pragma unroll
        for (int k = 0; k < 16; k++) {
            float4 a0 = *(const float4*)(&As[buf][k][ty * 8]);
            float4 a1 = *(const float4*)(&As[buf][k][ty * 8 + 4]);
            ulonglong2 b0 = *(const ulonglong2*)(&Bs[buf][k][tx * 8]);
            ulonglong2 b1 = *(const ulonglong2*)(&Bs[buf][k][tx * 8 + 4]);
            float av[8] = {a0.x, a0.y, a0.z, a0.w, a1.x, a1.y, a1.z, a1.w};
#pragma unroll
            for (int i = 0; i < 8; i++) {
                unsigned long long ad = pk2(av[i], av[i]);
                fma2(acc[i][0], ad, b0.x);
                fma2(acc[i][1], ad, b0.y);
                fma2(acc[i][2], ad, b1.x);
                fma2(acc[i][3], ad, b1.y);
            }
        }
        if (kt + 1 < KT) {
            int nb = buf ^ 1;
            As[nb][lcol + 0][lrow]      = pa0.x; As[nb][lcol + 1][lrow]      = pa0.y;
            As[nb][lcol + 2][lrow]      = pa0.z; As[nb][lcol + 3][lrow]      = pa0.w;
            As[nb][lcol + 0][lrow + 64] = pa1.x; As[nb][lcol + 1][lrow + 64] = pa1.y;
            As[nb][lcol + 2][lrow + 64] = pa1.z; As[nb][lcol + 3][lrow + 64] = pa1.w;
            Bs[nb][lcol + 0][lrow]      = pb0.x; Bs[nb][lcol + 1][lrow]      = pb0.y;
            Bs[nb][lcol + 2][lrow]      = pb0.z; Bs[nb][lcol + 3][lrow]      = pb0.w;
            Bs[nb][lcol + 0][lrow + 64] = pb1.x; Bs[nb][lcol + 1][lrow + 64] = pb1.y;
            Bs[nb][lcol + 2][lrow + 64] = pb1.z; Bs[nb][lcol + 3][lrow + 64] = pb1.w;
            __syncthreads();
            buf = nb;
        }
    }

    // ---- epilogue ----
    float c[8][8];
#pragma unroll
    for (int i = 0; i < 8; i++)
#pragma unroll
        for (int j = 0; j < 4; j++) upk2(acc[i][j], c[i][2 * j], c[i][2 * j + 1]);

    const int row0 = blockIdx.y * 128 + ty * 8;
    const int col0 = blockIdx.x * 128 + tx * 8;

    float4 bb0 = *(const float4*)(bias + col0);
    float4 bb1 = *(const float4*)(bias + col0 + 4);
    float bv[8] = {bb0.x, bb0.y, bb0.z, bb0.w, bb1.x, bb1.y, bb1.z, bb1.w};

    if (MODE == 0) {
        const bool isA = (col0 < DIN);
        float* base = isA ? g_A : g_B;
        const int cc = isA ? col0 : (col0 - DIN);
#pragma unroll
        for (int i = 0; i < 8; i++) {
            float o[8];
#pragma unroll
            for (int j = 0; j < 8; j++) {
                float v = c[i][j] + bv[j];
                float s = __fdividef(1.0f, 1.0f + __expf(-v));
                o[j] = isA ? s : v * s;   // sigmoid | silu
            }
            float* p = base + (size_t)(row0 + i) * DIN + cc;
            *(float4*)(p)     = make_float4(o[0], o[1], o[2], o[3]);
            *(float4*)(p + 4) = make_float4(o[4], o[5], o[6], o[7]);
        }
    } else {
#pragma unroll
        for (int i = 0; i < 8; i++) {
            size_t off = (size_t)(row0 + i) * Nv + col0;
            float4 x0 = *(const float4*)(Xres + off);
            float4 x1 = *(const float4*)(Xres + off + 4);
            float4 o0, o1;
            o0.x = c[i][0] + bv[0] + x0.x;
            o0.y = c[i][1] + bv[1] + x0.y;
            o0.z = c[i][2] + bv[2] + x0.z;
            o0.w = c[i][3] + bv[3] + x0.w;
            o1.x = c[i][4] + bv[4] + x1.x;
            o1.y = c[i][5] + bv[5] + x1.y;
            o1.z = c[i][6] + bv[6] + x1.z;
            o1.w = c[i][7] + bv[7] + x1.w;
            *(float4*)(outC + off)     = o0;
            *(float4*)(outC + off + 4) = o1;
        }
    }
}

// ---------------------------------------------------------------------------
// Kernel 3: recurrent scan. One thread per (batch, channel); h written into
// g_B in place. Coalesced: consecutive threads = consecutive channels.
// ---------------------------------------------------------------------------
__global__ void scan_kernel(const float* __restrict__ h_prev,
                            float* __restrict__ hlast_out) {
    int t = blockIdx.x * blockDim.x + threadIdx.x;
    if (t >= BSZ * DIN) return;
    int b = t / DIN;
    int e = t - b * DIN;

    float h = h_prev[t];
    size_t idx = (size_t)b * SEQ * DIN + e;
#pragma unroll 8
    for (int n = 0; n < SEQ; n++) {
        float a  = g_A[idx];
        float bb = g_B[idx];
        h = fmaf(a, h, bb);
        g_B[idx] = h;
        idx += DIN;
    }
    hlast_out[t] = h;
}

// ---------------------------------------------------------------------------
// Launch
// ---------------------------------------------------------------------------
extern "C" void kernel_launch(void* const* d_in, const int* in_sizes, int n_in,
                              void* d_out, int out_size) {
    const float* x      = (const float*)d_in[0];   // (4, 8192, 1024)
    const float* h_prev = (const float*)d_in[1];   // (4, 2048)
    const float* norm_w = (const float*)d_in[2];   // (1024,)
    const float* W_in   = (const float*)d_in[3];   // (4096, 1024)
    const float* b_in   = (const float*)d_in[4];   // (4096,)
    const float* W_out  = (const float*)d_in[5];   // (1024, 2048)
    const float* b_out  = (const float*)d_in[6];   // (1024,)
    float* out = (float*)d_out;                    // out (4,8192,1024) then h_last (4,2048)

    float* pXN;
    cudaGetSymbolAddress((void**)&pXN, g_XN);
    (void)pXN; (void)in_sizes; (void)n_in; (void)out_size;

    // 1. RMSNorm: 32768 rows, 1 warp each
    rmsnorm_kernel<<<MTOK / 8, 256>>>(x, norm_w, pXN);

    // 2. GEMM1 + gate activations: [32768 x 1024] * [4096 x 1024]^T
    dim3 g1((2 * DIN) / 128, MTOK / 128);
    sgemm_kernel<0, 2 * DIN, DIM><<<g1, 256>>>(W_in, b_in, nullptr, nullptr);

    // 3. Recurrent scan (h stored in g_B in place, h_last to tail of d_out)
    scan_kernel<<<(BSZ * DIN) / 128, 128>>>(h_prev, out + (size_t)MTOK * DIM);

    // 4. GEMM2 + bias + residual: [32768 x 2048] * [1024 x 2048]^T + x
    dim3 g2(DIM / 128, MTOK / 128);
    sgemm_kernel<1, DIM, DIN><<<g2, 256>>>(W_out, b_out, x, out);
}

// round 16
// speedup vs baseline: 1.1671x; 1.1210x over previous
#include <cuda_runtime.h>
#include <math.h>

// Problem constants (fixed shapes from setup_inputs)
#define BSZ   4
#define SEQ   8192
#define DIM   1024
#define DIN   2048
#define MTOK  (BSZ * SEQ)          // 32768 tokens

// ---------------------------------------------------------------------------
// Scratch (no cudaMalloc allowed): 134MB + 268MB + 268MB
// ---------------------------------------------------------------------------
__device__ float g_XN[(size_t)MTOK * DIM];   // rmsnorm(x)
__device__ float g_A [(size_t)MTOK * DIN];   // sigmoid gate a
__device__ float g_B [(size_t)MTOK * DIN];   // silu b, then h (in place)

// ---------------------------------------------------------------------------
// Packed f32x2 helpers (B300: FFMA2 doubles FP32 throughput vs scalar FFMA)
// ---------------------------------------------------------------------------
__device__ __forceinline__ unsigned long long pk2(float lo, float hi) {
    unsigned long long r;
    asm("mov.b64 %0, {%1, %2};" : "=l"(r) : "f"(lo), "f"(hi));
    return r;
}
__device__ __forceinline__ void fma2(unsigned long long& c,
                                     unsigned long long a,
                                     unsigned long long b) {
    asm("fma.rn.f32x2 %0, %1, %2, %3;" : "=l"(c) : "l"(a), "l"(b), "l"(c));
}
__device__ __forceinline__ void upk2(unsigned long long v, float& lo, float& hi) {
    asm("mov.b64 {%0, %1}, %2;" : "=f"(lo), "=f"(hi) : "l"(v));
}

// ---------------------------------------------------------------------------
// Kernel 1: RMSNorm. One warp per token row (D=1024 = 32 lanes x 8 float4).
// ---------------------------------------------------------------------------
__global__ void rmsnorm_kernel(const float* __restrict__ x,
                               const float* __restrict__ w,
                               float* __restrict__ xn) {
    int gwarp = (blockIdx.x * blockDim.x + threadIdx.x) >> 5;
    int lane  = threadIdx.x & 31;
    if (gwarp >= MTOK) return;

    const float4* xr = reinterpret_cast<const float4*>(x) + (size_t)gwarp * (DIM / 4);
    float4 v[8];
    float ss = 0.0f;
#pragma unroll
    for (int j = 0; j < 8; j++) {
        v[j] = xr[lane + j * 32];
        ss += v[j].x * v[j].x + v[j].y * v[j].y + v[j].z * v[j].z + v[j].w * v[j].w;
    }
#pragma unroll
    for (int o = 16; o > 0; o >>= 1) ss += __shfl_xor_sync(0xffffffffu, ss, o);

    float rstd = rsqrtf(ss * (1.0f / DIM) + 1e-6f);

    const float4* wr = reinterpret_cast<const float4*>(w);
    float4* xo = reinterpret_cast<float4*>(xn) + (size_t)gwarp * (DIM / 4);
#pragma unroll
    for (int j = 0; j < 8; j++) {
        float4 wv = wr[lane + j * 32];
        float4 o;
        o.x = v[j].x * rstd * wv.x;
        o.y = v[j].y * rstd * wv.y;
        o.z = v[j].z * rstd * wv.z;
        o.w = v[j].w * rstd * wv.w;
        xo[lane + j * 32] = o;
    }
}

// ---------------------------------------------------------------------------
// SGEMM: C[M,N] = A[M,K] (row-major) * Bw[N,K]^T (row-major, K contiguous).
// BM=BN=128, BK=16, thread tile 8x8, 256 threads, double-buffered smem,
// FFMA2 inner product.
//
// N-fragment layout (R15 -> R16 change): each thread owns two SPLIT float4
// column groups, cols [tx*4, tx*4+4) and [64+tx*4, 64+tx*4+4), instead of one
// contiguous 8-wide group at tx*8. LDS.128 lane stride drops 8 words -> 4
// words: 4-way bank conflict -> 2-way (the 256B-unique floor).
//
// MODE 0: A = g_XN, epilogue = +bias, sigmoid -> g_A / silu -> g_B
// MODE 1: A = g_B (h), epilogue = +bias +x residual -> outC
// ---------------------------------------------------------------------------
template <int MODE, int Nv, int Kv>
__global__ __launch_bounds__(256, 2)
void sgemm_kernel(const float* __restrict__ Bw,
                  const float* __restrict__ bias,
                  const float* __restrict__ Xres,
                  float* __restrict__ outC) {
    __shared__ __align__(16) float As[2][16][132];
    __shared__ __align__(16) float Bs[2][16][132];

    const float* __restrict__ A = (MODE == 0) ? g_XN : g_B;

    const int tid  = threadIdx.x;
    const int tx   = tid & 15;
    const int ty   = tid >> 4;
    const int lrow = tid >> 2;          // 0..63
    const int lcol = (tid & 3) << 2;    // 0,4,8,12

    const size_t aBase = (size_t)(blockIdx.y * 128 + lrow) * Kv + lcol;
    const size_t bBase = (size_t)(blockIdx.x * 128 + lrow) * Kv + lcol;

    unsigned long long acc[8][4];
#pragma unroll
    for (int i = 0; i < 8; i++)
#pragma unroll
        for (int j = 0; j < 4; j++) acc[i][j] = 0ull;

    // ---- preload tile 0 ----
    float4 pa0 = *(const float4*)(A  + aBase);
    float4 pa1 = *(const float4*)(A  + aBase + (size_t)64 * Kv);
    float4 pb0 = *(const float4*)(Bw + bBase);
    float4 pb1 = *(const float4*)(Bw + bBase + (size_t)64 * Kv);

    As[0][lcol + 0][lrow]      = pa0.x; As[0][lcol + 1][lrow]      = pa0.y;
    As[0][lcol + 2][lrow]      = pa0.z; As[0][lcol + 3][lrow]      = pa0.w;
    As[0][lcol + 0][lrow + 64] = pa1.x; As[0][lcol + 1][lrow + 64] = pa1.y;
    As[0][lcol + 2][lrow + 64] = pa1.z; As[0][lcol + 3][lrow + 64] = pa1.w;
    Bs[0][lcol + 0][lrow]      = pb0.x; Bs[0][lcol + 1][lrow]      = pb0.y;
    Bs[0][lcol + 2][lrow]      = pb0.z; Bs[0][lcol + 3][lrow]      = pb0.w;
    Bs[0][lcol + 0][lrow + 64] = pb1.x; Bs[0][lcol + 1][lrow + 64] = pb1.y;
    Bs[0][lcol + 2][lrow + 64] = pb1.z; Bs[0][lcol + 3][lrow + 64] = pb1.w;
    __syncthreads();

    const int KT = Kv >> 4;
    int buf = 0;
    for (int kt = 0; kt < KT; kt++) {
        if (kt + 1 < KT) {
            size_t off = (size_t)(kt + 1) * 16;
            pa0 = *(const float4*)(A  + aBase + off);
            pa1 = *(const float4*)(A  + aBase + off + (size_t)64 * Kv);
            pb0 = *(const float4*)(Bw + bBase + off);
            pb1 = *(const float4*)(Bw + bBase + off + (size_t)64 * Kv);
        }
#pragma unroll
        for (int k = 0; k < 16; k++) {
            float4 a0 = *(const float4*)(&As[buf][k][ty * 8]);
            float4 a1 = *(const float4*)(&As[buf][k][ty * 8 + 4]);
            // Split N-fragments: stride-4 lane addressing (2-way conflict floor)
            ulonglong2 b0 = *(const ulonglong2*)(&Bs[buf][k][tx * 4]);
            ulonglong2 b1 = *(const ulonglong2*)(&Bs[buf][k][64 + tx * 4]);
            float av[8] = {a0.x, a0.y, a0.z, a0.w, a1.x, a1.y, a1.z, a1.w};
#pragma unroll
            for (int i = 0; i < 8; i++) {
                unsigned long long ad = pk2(av[i], av[i]);
                fma2(acc[i][0], ad, b0.x);
                fma2(acc[i][1], ad, b0.y);
                fma2(acc[i][2], ad, b1.x);
                fma2(acc[i][3], ad, b1.y);
            }
        }
        if (kt + 1 < KT) {
            int nb = buf ^ 1;
            As[nb][lcol + 0][lrow]      = pa0.x; As[nb][lcol + 1][lrow]      = pa0.y;
            As[nb][lcol + 2][lrow]      = pa0.z; As[nb][lcol + 3][lrow]      = pa0.w;
            As[nb][lcol + 0][lrow + 64] = pa1.x; As[nb][lcol + 1][lrow + 64] = pa1.y;
            As[nb][lcol + 2][lrow + 64] = pa1.z; As[nb][lcol + 3][lrow + 64] = pa1.w;
            Bs[nb][lcol + 0][lrow]      = pb0.x; Bs[nb][lcol + 1][lrow]      = pb0.y;
            Bs[nb][lcol + 2][lrow]      = pb0.z; Bs[nb][lcol + 3][lrow]      = pb0.w;
            Bs[nb][lcol + 0][lrow + 64] = pb1.x; Bs[nb][lcol + 1][lrow + 64] = pb1.y;
            Bs[nb][lcol + 2][lrow + 64] = pb1.z; Bs[nb][lcol + 3][lrow + 64] = pb1.w;
            __syncthreads();
            buf = nb;
        }
    }

    // ---- epilogue ----
    // c[i][0..3] -> cols colA+0..3 ; c[i][4..7] -> cols colB+0..3
    float c[8][8];
#pragma unroll
    for (int i = 0; i < 8; i++)
#pragma unroll
        for (int j = 0; j < 4; j++) upk2(acc[i][j], c[i][2 * j], c[i][2 * j + 1]);

    const int row0 = blockIdx.y * 128 + ty * 8;
    const int colA = blockIdx.x * 128 + tx * 4;
    const int colB = colA + 64;

    float4 bb0 = *(const float4*)(bias + colA);
    float4 bb1 = *(const float4*)(bias + colB);
    float bv[8] = {bb0.x, bb0.y, bb0.z, bb0.w, bb1.x, bb1.y, bb1.z, bb1.w};

    if (MODE == 0) {
        // Entire 128-col block is on one side of the DIN boundary (2048 % 128 == 0)
        const bool isA = (colA < DIN);
        float* base = isA ? g_A : g_B;
        const int ccA = isA ? colA : (colA - DIN);
        const int ccB = isA ? colB : (colB - DIN);
#pragma unroll
        for (int i = 0; i < 8; i++) {
            float o[8];
#pragma unroll
            for (int j = 0; j < 8; j++) {
                float v = c[i][j] + bv[j];
                float s = __fdividef(1.0f, 1.0f + __expf(-v));
                o[j] = isA ? s : v * s;   // sigmoid | silu
            }
            float* pr = base + (size_t)(row0 + i) * DIN;
            *(float4*)(pr + ccA) = make_float4(o[0], o[1], o[2], o[3]);
            *(float4*)(pr + ccB) = make_float4(o[4], o[5], o[6], o[7]);
        }
    } else {
#pragma unroll
        for (int i = 0; i < 8; i++) {
            size_t rowOff = (size_t)(row0 + i) * Nv;
            float4 x0 = *(const float4*)(Xres + rowOff + colA);
            float4 x1 = *(const float4*)(Xres + rowOff + colB);
            float4 o0, o1;
            o0.x = c[i][0] + bv[0] + x0.x;
            o0.y = c[i][1] + bv[1] + x0.y;
            o0.z = c[i][2] + bv[2] + x0.z;
            o0.w = c[i][3] + bv[3] + x0.w;
            o1.x = c[i][4] + bv[4] + x1.x;
            o1.y = c[i][5] + bv[5] + x1.y;
            o1.z = c[i][6] + bv[6] + x1.z;
            o1.w = c[i][7] + bv[7] + x1.w;
            *(float4*)(outC + rowOff + colA) = o0;
            *(float4*)(outC + rowOff + colB) = o1;
        }
    }
}

// ---------------------------------------------------------------------------
// Kernel 3: recurrent scan. One thread per (batch, channel); h written into
// g_B in place. Coalesced: consecutive threads = consecutive channels.
// ---------------------------------------------------------------------------
__global__ void scan_kernel(const float* __restrict__ h_prev,
                            float* __restrict__ hlast_out) {
    int t = blockIdx.x * blockDim.x + threadIdx.x;
    if (t >= BSZ * DIN) return;
    int b = t / DIN;
    int e = t - b * DIN;

    float h = h_prev[t];
    size_t idx = (size_t)b * SEQ * DIN + e;
#pragma unroll 8
    for (int n = 0; n < SEQ; n++) {
        float a  = g_A[idx];
        float bb = g_B[idx];
        h = fmaf(a, h, bb);
        g_B[idx] = h;
        idx += DIN;
    }
    hlast_out[t] = h;
}

// ---------------------------------------------------------------------------
// Launch
// ---------------------------------------------------------------------------
extern "C" void kernel_launch(void* const* d_in, const int* in_sizes, int n_in,
                              void* d_out, int out_size) {
    const float* x      = (const float*)d_in[0];   // (4, 8192, 1024)
    const float* h_prev = (const float*)d_in[1];   // (4, 2048)
    const float* norm_w = (const float*)d_in[2];   // (1024,)
    const float* W_in   = (const float*)d_in[3];   // (4096, 1024)
    const float* b_in   = (const float*)d_in[4];   // (4096,)
    const float* W_out  = (const float*)d_in[5];   // (1024, 2048)
    const float* b_out  = (const float*)d_in[6];   // (1024,)
    float* out = (float*)d_out;                    // out (4,8192,1024) then h_last (4,2048)

    float* pXN;
    cudaGetSymbolAddress((void**)&pXN, g_XN);
    (void)pXN; (void)in_sizes; (void)n_in; (void)out_size;

    // 1. RMSNorm: 32768 rows, 1 warp each
    rmsnorm_kernel<<<MTOK / 8, 256>>>(x, norm_w, pXN);

    // 2. GEMM1 + gate activations: [32768 x 1024] * [4096 x 1024]^T
    dim3 g1((2 * DIN) / 128, MTOK / 128);
    sgemm_kernel<0, 2 * DIN, DIM><<<g1, 256>>>(W_in, b_in, nullptr, nullptr);

    // 3. Recurrent scan (h stored in g_B in place, h_last to tail of d_out)
    scan_kernel<<<(BSZ * DIN) / 128, 128>>>(h_prev, out + (size_t)MTOK * DIM);

    // 4. GEMM2 + bias + residual: [32768 x 2048] * [1024 x 2048]^T + x
    dim3 g2(DIM / 128, MTOK / 128);
    sgemm_kernel<1, DIM, DIN><<<g2, 256>>>(W_out, b_out, x, out);
}

// round 17
// speedup vs baseline: 1.1683x; 1.0010x over previous
#include <cuda_runtime.h>
#include <math.h>

// Problem constants (fixed shapes from setup_inputs)
#define BSZ   4
#define SEQ   8192
#define DIM   1024
#define DIN   2048
#define MTOK  (BSZ * SEQ)          // 32768 tokens

// ---------------------------------------------------------------------------
// Scratch (no cudaMalloc allowed): 134MB + 268MB + 268MB
// ---------------------------------------------------------------------------
__device__ float g_XN[(size_t)MTOK * DIM];   // rmsnorm(x)
__device__ float g_A [(size_t)MTOK * DIN];   // sigmoid gate a
__device__ float g_B [(size_t)MTOK * DIN];   // silu b, then h (in place)

// ---------------------------------------------------------------------------
// Packed f32x2 helpers (B300: FFMA2 doubles FP32 throughput vs scalar FFMA)
// ---------------------------------------------------------------------------
__device__ __forceinline__ unsigned long long pk2(float lo, float hi) {
    unsigned long long r;
    asm("mov.b64 %0, {%1, %2};" : "=l"(r) : "f"(lo), "f"(hi));
    return r;
}
__device__ __forceinline__ void fma2(unsigned long long& c,
                                     unsigned long long a,
                                     unsigned long long b) {
    asm("fma.rn.f32x2 %0, %1, %2, %3;" : "=l"(c) : "l"(a), "l"(b), "l"(c));
}
__device__ __forceinline__ void upk2(unsigned long long v, float& lo, float& hi) {
    asm("mov.b64 {%0, %1}, %2;" : "=f"(lo), "=f"(hi) : "l"(v));
}

// ---------------------------------------------------------------------------
// Kernel 1: RMSNorm. One warp per token row (D=1024 = 32 lanes x 8 float4).
// ---------------------------------------------------------------------------
__global__ void rmsnorm_kernel(const float* __restrict__ x,
                               const float* __restrict__ w,
                               float* __restrict__ xn) {
    int gwarp = (blockIdx.x * blockDim.x + threadIdx.x) >> 5;
    int lane  = threadIdx.x & 31;
    if (gwarp >= MTOK) return;

    const float4* xr = reinterpret_cast<const float4*>(x) + (size_t)gwarp * (DIM / 4);
    float4 v[8];
    float ss = 0.0f;
#pragma unroll
    for (int j = 0; j < 8; j++) {
        v[j] = xr[lane + j * 32];
        ss += v[j].x * v[j].x + v[j].y * v[j].y + v[j].z * v[j].z + v[j].w * v[j].w;
    }
#pragma unroll
    for (int o = 16; o > 0; o >>= 1) ss += __shfl_xor_sync(0xffffffffu, ss, o);

    float rstd = rsqrtf(ss * (1.0f / DIM) + 1e-6f);

    const float4* wr = reinterpret_cast<const float4*>(w);
    float4* xo = reinterpret_cast<float4*>(xn) + (size_t)gwarp * (DIM / 4);
#pragma unroll
    for (int j = 0; j < 8; j++) {
        float4 wv = wr[lane + j * 32];
        float4 o;
        o.x = v[j].x * rstd * wv.x;
        o.y = v[j].y * rstd * wv.y;
        o.z = v[j].z * rstd * wv.z;
        o.w = v[j].w * rstd * wv.w;
        xo[lane + j * 32] = o;
    }
}

// ---------------------------------------------------------------------------
// SGEMM: C[M,N] = A[M,K] (row-major) * Bw[N,K]^T (row-major, K contiguous).
// BM=BN=128, BK=16, thread tile 8x8, 256 threads, double-buffered smem,
// FFMA2 inner product.
//
// N-fragment layout (R15 -> R16 change): each thread owns two SPLIT float4
// column groups, cols [tx*4, tx*4+4) and [64+tx*4, 64+tx*4+4), instead of one
// contiguous 8-wide group at tx*8. LDS.128 lane stride drops 8 words -> 4
// words: 4-way bank conflict -> 2-way (the 256B-unique floor).
//
// MODE 0: A = g_XN, epilogue = +bias, sigmoid -> g_A / silu -> g_B
// MODE 1: A = g_B (h), epilogue = +bias +x residual -> outC
// ---------------------------------------------------------------------------
template <int MODE, int Nv, int Kv>
__global__ __launch_bounds__(256, 2)
void sgemm_kernel(const float* __restrict__ Bw,
                  const float* __restrict__ bias,
                  const float* __restrict__ Xres,
                  float* __restrict__ outC) {
    __shared__ __align__(16) float As[2][16][132];
    __shared__ __align__(16) float Bs[2][16][132];

    const float* __restrict__ A = (MODE == 0) ? g_XN : g_B;

    const int tid  = threadIdx.x;
    const int tx   = tid & 15;
    const int ty   = tid >> 4;
    const int lrow = tid >> 2;          // 0..63
    const int lcol = (tid & 3) << 2;    // 0,4,8,12

    const size_t aBase = (size_t)(blockIdx.y * 128 + lrow) * Kv + lcol;
    const size_t bBase = (size_t)(blockIdx.x * 128 + lrow) * Kv + lcol;

    unsigned long long acc[8][4];
#pragma unroll
    for (int i = 0; i < 8; i++)
#pragma unroll
        for (int j = 0; j < 4; j++) acc[i][j] = 0ull;

    // ---- preload tile 0 ----
    float4 pa0 = *(const float4*)(A  + aBase);
    float4 pa1 = *(const float4*)(A  + aBase + (size_t)64 * Kv);
    float4 pb0 = *(const float4*)(Bw + bBase);
    float4 pb1 = *(const float4*)(Bw + bBase + (size_t)64 * Kv);

    As[0][lcol + 0][lrow]      = pa0.x; As[0][lcol + 1][lrow]      = pa0.y;
    As[0][lcol + 2][lrow]      = pa0.z; As[0][lcol + 3][lrow]      = pa0.w;
    As[0][lcol + 0][lrow + 64] = pa1.x; As[0][lcol + 1][lrow + 64] = pa1.y;
    As[0][lcol + 2][lrow + 64] = pa1.z; As[0][lcol + 3][lrow + 64] = pa1.w;
    Bs[0][lcol + 0][lrow]      = pb0.x; Bs[0][lcol + 1][lrow]      = pb0.y;
    Bs[0][lcol + 2][lrow]      = pb0.z; Bs[0][lcol + 3][lrow]      = pb0.w;
    Bs[0][lcol + 0][lrow + 64] = pb1.x; Bs[0][lcol + 1][lrow + 64] = pb1.y;
    Bs[0][lcol + 2][lrow + 64] = pb1.z; Bs[0][lcol + 3][lrow + 64] = pb1.w;
    __syncthreads();

    const int KT = Kv >> 4;
    int buf = 0;
    for (int kt = 0; kt < KT; kt++) {
        if (kt + 1 < KT) {
            size_t off = (size_t)(kt + 1) * 16;
            pa0 = *(const float4*)(A  + aBase + off);
            pa1 = *(const float4*)(A  + aBase + off + (size_t)64 * Kv);
            pb0 = *(const float4*)(Bw + bBase + off);
            pb1 = *(const float4*)(Bw + bBase + off + (size_t)64 * Kv);
        }
#pragma unroll
        for (int k = 0; k < 16; k++) {
            float4 a0 = *(const float4*)(&As[buf][k][ty * 8]);
            float4 a1 = *(const float4*)(&As[buf][k][ty * 8 + 4]);
            // Split N-fragments: stride-4 lane addressing (2-way conflict floor)
            ulonglong2 b0 = *(const ulonglong2*)(&Bs[buf][k][tx * 4]);
            ulonglong2 b1 = *(const ulonglong2*)(&Bs[buf][k][64 + tx * 4]);
            float av[8] = {a0.x, a0.y, a0.z, a0.w, a1.x, a1.y, a1.z, a1.w};
#pragma unroll
            for (int i = 0; i < 8; i++) {
                unsigned long long ad = pk2(av[i], av[i]);
                fma2(acc[i][0], ad, b0.x);
                fma2(acc[i][1], ad, b0.y);
                fma2(acc[i][2], ad, b1.x);
                fma2(acc[i][3], ad, b1.y);
            }
        }
        if (kt + 1 < KT) {
            int nb = buf ^ 1;
            As[nb][lcol + 0][lrow]      = pa0.x; As[nb][lcol + 1][lrow]      = pa0.y;
            As[nb][lcol + 2][lrow]      = pa0.z; As[nb][lcol + 3][lrow]      = pa0.w;
            As[nb][lcol + 0][lrow + 64] = pa1.x; As[nb][lcol + 1][lrow + 64] = pa1.y;
            As[nb][lcol + 2][lrow + 64] = pa1.z; As[nb][lcol + 3][lrow + 64] = pa1.w;
            Bs[nb][lcol + 0][lrow]      = pb0.x; Bs[nb][lcol + 1][lrow]      = pb0.y;
            Bs[nb][lcol + 2][lrow]      = pb0.z; Bs[nb][lcol + 3][lrow]      = pb0.w;
            Bs[nb][lcol + 0][lrow + 64] = pb1.x; Bs[nb][lcol + 1][lrow + 64] = pb1.y;
            Bs[nb][lcol + 2][lrow + 64] = pb1.z; Bs[nb][lcol + 3][lrow + 64] = pb1.w;
            __syncthreads();
            buf = nb;
        }
    }

    // ---- epilogue ----
    // c[i][0..3] -> cols colA+0..3 ; c[i][4..7] -> cols colB+0..3
    float c[8][8];
#pragma unroll
    for (int i = 0; i < 8; i++)
#pragma unroll
        for (int j = 0; j < 4; j++) upk2(acc[i][j], c[i][2 * j], c[i][2 * j + 1]);

    const int row0 = blockIdx.y * 128 + ty * 8;
    const int colA = blockIdx.x * 128 + tx * 4;
    const int colB = colA + 64;

    float4 bb0 = *(const float4*)(bias + colA);
    float4 bb1 = *(const float4*)(bias + colB);
    float bv[8] = {bb0.x, bb0.y, bb0.z, bb0.w, bb1.x, bb1.y, bb1.z, bb1.w};

    if (MODE == 0) {
        // Entire 128-col block is on one side of the DIN boundary (2048 % 128 == 0)
        const bool isA = (colA < DIN);
        float* base = isA ? g_A : g_B;
        const int ccA = isA ? colA : (colA - DIN);
        const int ccB = isA ? colB : (colB - DIN);
#pragma unroll
        for (int i = 0; i < 8; i++) {
            float o[8];
#pragma unroll
            for (int j = 0; j < 8; j++) {
                float v = c[i][j] + bv[j];
                float s = __fdividef(1.0f, 1.0f + __expf(-v));
                o[j] = isA ? s : v * s;   // sigmoid | silu
            }
            float* pr = base + (size_t)(row0 + i) * DIN;
            *(float4*)(pr + ccA) = make_float4(o[0], o[1], o[2], o[3]);
            *(float4*)(pr + ccB) = make_float4(o[4], o[5], o[6], o[7]);
        }
    } else {
#pragma unroll
        for (int i = 0; i < 8; i++) {
            size_t rowOff = (size_t)(row0 + i) * Nv;
            float4 x0 = *(const float4*)(Xres + rowOff + colA);
            float4 x1 = *(const float4*)(Xres + rowOff + colB);
            float4 o0, o1;
            o0.x = c[i][0] + bv[0] + x0.x;
            o0.y = c[i][1] + bv[1] + x0.y;
            o0.z = c[i][2] + bv[2] + x0.z;
            o0.w = c[i][3] + bv[3] + x0.w;
            o1.x = c[i][4] + bv[4] + x1.x;
            o1.y = c[i][5] + bv[5] + x1.y;
            o1.z = c[i][6] + bv[6] + x1.z;
            o1.w = c[i][7] + bv[7] + x1.w;
            *(float4*)(outC + rowOff + colA) = o0;
            *(float4*)(outC + rowOff + colB) = o1;
        }
    }
}

// ---------------------------------------------------------------------------
// Kernel 3: recurrent scan. One thread per (batch, channel); h written into
// g_B in place. Coalesced: consecutive threads = consecutive channels.
// ---------------------------------------------------------------------------
__global__ void scan_kernel(const float* __restrict__ h_prev,
                            float* __restrict__ hlast_out) {
    int t = blockIdx.x * blockDim.x + threadIdx.x;
    if (t >= BSZ * DIN) return;
    int b = t / DIN;
    int e = t - b * DIN;

    float h = h_prev[t];
    size_t idx = (size_t)b * SEQ * DIN + e;
#pragma unroll 8
    for (int n = 0; n < SEQ; n++) {
        float a  = g_A[idx];
        float bb = g_B[idx];
        h = fmaf(a, h, bb);
        g_B[idx] = h;
        idx += DIN;
    }
    hlast_out[t] = h;
}

// ---------------------------------------------------------------------------
// Launch
// ---------------------------------------------------------------------------
extern "C" void kernel_launch(void* const* d_in, const int* in_sizes, int n_in,
                              void* d_out, int out_size) {
    const float* x      = (const float*)d_in[0];   // (4, 8192, 1024)
    const float* h_prev = (const float*)d_in[1];   // (4, 2048)
    const float* norm_w = (const float*)d_in[2];   // (1024,)
    const float* W_in   = (const float*)d_in[3];   // (4096, 1024)
    const float* b_in   = (const float*)d_in[4];   // (4096,)
    const float* W_out  = (const float*)d_in[5];   // (1024, 2048)
    const float* b_out  = (const float*)d_in[6];   // (1024,)
    float* out = (float*)d_out;                    // out (4,8192,1024) then h_last (4,2048)

    float* pXN;
    cudaGetSymbolAddress((void**)&pXN, g_XN);
    (void)pXN; (void)in_sizes; (void)n_in; (void)out_size;

    // 1. RMSNorm: 32768 rows, 1 warp each
    rmsnorm_kernel<<<MTOK / 8, 256>>>(x, norm_w, pXN);

    // 2. GEMM1 + gate activations: [32768 x 1024] * [4096 x 1024]^T
    dim3 g1((2 * DIN) / 128, MTOK / 128);
    sgemm_kernel<0, 2 * DIN, DIM><<<g1, 256>>>(W_in, b_in, nullptr, nullptr);

    // 3. Recurrent scan (h stored in g_B in place, h_last to tail of d_out)
    scan_kernel<<<(BSZ * DIN) / 128, 128>>>(h_prev, out + (size_t)MTOK * DIM);

    // 4. GEMM2 + bias + residual: [32768 x 2048] * [1024 x 2048]^T + x
    dim3 g2(DIM / 128, MTOK / 128);
    sgemm_kernel<1, DIM, DIN><<<g2, 256>>>(W_out, b_out, x, out);
}